// round 6
// baseline (speedup 1.0000x reference)
#include <cuda_runtime.h>

namespace {

constexpr int RAD   = 7;          // N = 2*ceil(2.5)+1 = 7
constexpr int TBX   = 32;         // threads x
constexpr int TBY   = 4;          // threads y
constexpr int PXY   = 2;          // pixels per thread in y
constexpr int TILEY = TBY * PXY;  // 8 output rows per block
constexpr int SW    = TBX + 2*RAD;    // 46
constexpr int SH    = TILEY + 2*RAD;  // 22
constexpr int IMH   = 1080;
constexpr int IMW   = 1920;
constexpr int CH    = 11;

#define EPSF          1e-4f
#define LOG2E_F       1.4426950408889634f
#define NHALF_LOG2E_F 0.7213475204444817f   /* 0.5*log2(e) */

__device__ __forceinline__ float ex2f_(float x) {
    float y;
    asm("ex2.approx.f32 %0, %1;" : "=f"(y) : "f"(x));
    return y;
}

// One tap applied to one pixel's accumulators. dsi/dist are compile-time
// constants after full unroll.
__device__ __forceinline__ void tap_(
    const float4 nz, const float4 cd,
    float Nx, float Ny, float Nz, float Zc, float dzc,
    float dsi, float dist,
    float& ar, float& ag, float& ab, float& aw)
{
    float dot = nz.x*Nx + nz.y*Ny + nz.z*Nz;
    float t = fminf(fmaxf(dot, EPSF), 1.0f);
    t = t*t; t = t*t; t = t*t; t = t*t; t = t*t; t = t*t; t = t*t; // ^128

    float den = fmaxf(dzc * dist, EPSF);
    float r   = __fdividef(fabsf(nz.w - Zc), den);
    float w   = ex2f_(fmaf(r, -LOG2E_F, -NHALF_LOG2E_F * dsi)) * t;

    ar = fmaf(cd.x, w, ar);
    ag = fmaf(cd.y, w, ag);
    ab = fmaf(cd.z, w, ab);
    aw += w;
}

} // namespace

__global__ void __launch_bounds__(TBX*TBY, 4)
BilateralDenoiser_44427141710593_kernel(const float* __restrict__ in,
                                        float* __restrict__ out)
{
    __shared__ float4 s_nz[SH * SW];   // (nrm.x, nrm.y, nrm.z, z)
    __shared__ float4 s_cd[SH * SW];   // (col.r, col.g, col.b, dz)

    const int bx  = blockIdx.x * TBX;
    const int by  = blockIdx.y * TILEY;
    const int tid = threadIdx.y * TBX + threadIdx.x;

    // Cooperative halo load; OOB -> zeros => dot=0 -> eps^128 underflows to 0
    // -> w=0, matching the reference's where(valid, ..., 0).
    #pragma unroll
    for (int i = tid; i < SH * SW; i += TBX * TBY) {
        const int ly = i / SW;
        const int lx = i - ly * SW;
        const int gy = by + ly - RAD;
        const int gx = bx + lx - RAD;
        float4 nz = make_float4(0.f, 0.f, 0.f, 0.f);
        float4 cd = make_float4(0.f, 0.f, 0.f, 0.f);
        if ((unsigned)gy < (unsigned)IMH && (unsigned)gx < (unsigned)IMW) {
            const float* p = in + ((size_t)gy * IMW + gx) * CH;
            cd.x = p[0]; cd.y = p[1]; cd.z = p[2];      // col
            nz.x = p[3]; nz.y = p[4]; nz.z = p[5];      // nrm
            nz.w = p[9];                                 // z
            cd.w = p[10];                                // dz
        }
        s_nz[i] = nz;
        s_cd[i] = cd;
    }
    __syncthreads();

    // Pixel0 center; pixel1 is one smem row below (+SW).
    const int c0 = (threadIdx.y * PXY + RAD) * SW + (threadIdx.x + RAD);
    const float4* __restrict__ snz = s_nz + c0;
    const float4* __restrict__ scd = s_cd + c0;

    const float4 n0 = snz[0];
    const float  dz0 = scd[0].w;
    const float4 n1 = snz[SW];
    const float  dz1 = scd[SW].w;

    float ar0=0.f, ag0=0.f, ab0=0.f, aw0=0.f;
    float ar1=0.f, ag1=0.f, ab1=0.f, aw1=0.f;

    // dy spans pixel0's [-7,7] and pixel1's [-7,7] (shifted by +1):
    // one shared load per (dy,dx) feeds both pixels.
    #pragma unroll
    for (int dy = -RAD; dy <= RAD + 1; ++dy) {
        #pragma unroll
        for (int dx = -RAD; dx <= RAD; ++dx) {
            const float4 nz = snz[dy*SW + dx];
            const float4 cd = scd[dy*SW + dx];

            if (dy <= RAD) {                       // compile-time predicate
                const int d0 = dy*dy + dx*dx;
                tap_(nz, cd, n0.x, n0.y, n0.z, n0.w, dz0,
                     (float)d0, sqrtf((float)d0), ar0, ag0, ab0, aw0);
            }
            if (dy >= -RAD + 1) {                  // compile-time predicate
                const int d1 = (dy-1)*(dy-1) + dx*dx;
                tap_(nz, cd, n1.x, n1.y, n1.z, n1.w, dz1,
                     (float)d1, sqrtf((float)d1), ar1, ag1, ab1, aw1);
            }
        }
    }

    const int gx = bx + threadIdx.x;
    const int gy0 = by + threadIdx.y * PXY;

    {
        const float inv = 1.0f / fmaxf(aw0, EPSF);
        float* o = out + ((size_t)gy0 * IMW + gx) * 3;
        o[0] = ar0 * inv; o[1] = ag0 * inv; o[2] = ab0 * inv;
    }
    {
        const float inv = 1.0f / fmaxf(aw1, EPSF);
        float* o = out + ((size_t)(gy0 + 1) * IMW + gx) * 3;
        o[0] = ar1 * inv; o[1] = ag1 * inv; o[2] = ab1 * inv;
    }
}

extern "C" void kernel_launch(void* const* d_in, const int* in_sizes, int n_in,
                              void* d_out, int out_size)
{
    const float* in = (const float*)d_in[0];
    float* out = (float*)d_out;
    dim3 block(TBX, TBY);
    dim3 grid(IMW / TBX, IMH / TILEY);   // 60 x 135, exact tiling
    BilateralDenoiser_44427141710593_kernel<<<grid, block>>>(in, out);
}

// round 7
// speedup vs baseline: 1.6582x; 1.6582x over previous
#include <cuda_runtime.h>

namespace {

constexpr int RAD   = 7;          // N = 2*ceil(2.5)+1 = 7
constexpr int TBX   = 32;         // threads x
constexpr int TBY   = 4;          // threads y
constexpr int PXY   = 2;          // pixels per thread in y
constexpr int TILEY = TBY * PXY;  // 8 output rows per block
constexpr int SW    = TBX + 2*RAD;    // 46
constexpr int SH    = TILEY + 2*RAD;  // 22
constexpr int IMH   = 1080;
constexpr int IMW   = 1920;
constexpr int CH    = 11;

#define EPSF          1e-4f
#define LOG2E_F       1.4426950408889634f
#define NHALF_LOG2E_F 0.7213475204444817f   /* 0.5*log2(e) */

__device__ __forceinline__ float ex2f_(float x) {
    float y;
    asm("ex2.approx.f32 %0, %1;" : "=f"(y) : "f"(x));
    return y;
}
__device__ __forceinline__ float lg2f_(float x) {
    float y;
    asm("lg2.approx.f32 %0, %1;" : "=f"(y) : "f"(x));
    return y;
}

// One tap for one pixel. dsi/dist are compile-time constants after unroll.
// w = exp(-d^2/2) * clip(dot,eps,1)^128 * exp(-|zt-z|/max(dz*d,eps))
//   = ex2( -d^2*log2e/2  +  128*lg2(sat(dot))  -  log2e*|zt-z|/den )
// sat(dot): dot<=0 -> lg2(0) = -inf -> ex2 = 0, identical to the reference's
// eps^128 fp32 underflow; dot>1 -> 1 -> lg2 = 0. Exact behavioral match.
__device__ __forceinline__ void tap_(
    const float4 nz, const float4 cd,
    float Nx, float Ny, float Nz, float Zc, float dzc,
    float dsi, float dist,
    float& ar, float& ag, float& ab, float& aw)
{
    float dot = __saturatef(nz.x*Nx + fmaf(nz.y, Ny, nz.z*Nz)); // FFMA.SAT
    float lt  = lg2f_(dot);

    float den = fmaxf(dzc * dist, EPSF);
    float r   = fabsf(nz.w - Zc) * __frcp_rn(den) /* MUFU.RCP via approx */;

    float arg = fmaf(lt, 128.0f, fmaf(r, -LOG2E_F, -NHALF_LOG2E_F * dsi));
    float w   = ex2f_(arg);

    ar = fmaf(cd.x, w, ar);
    ag = fmaf(cd.y, w, ag);
    ab = fmaf(cd.z, w, ab);
    aw += w;
}

} // namespace

__global__ void __launch_bounds__(TBX*TBY, 5)
BilateralDenoiser_44427141710593_kernel(const float* __restrict__ in,
                                        float* __restrict__ out)
{
    __shared__ float4 s_nz[SH * SW];   // (nrm.x, nrm.y, nrm.z, z)
    __shared__ float4 s_cd[SH * SW];   // (col.r, col.g, col.b, dz)

    const int bx  = blockIdx.x * TBX;
    const int by  = blockIdx.y * TILEY;
    const int tid = threadIdx.y * TBX + threadIdx.x;

    // Cooperative halo load; OOB -> zeros => dot=0 -> w=0 (matches reference).
    #pragma unroll
    for (int i = tid; i < SH * SW; i += TBX * TBY) {
        const int ly = i / SW;
        const int lx = i - ly * SW;
        const int gy = by + ly - RAD;
        const int gx = bx + lx - RAD;
        float4 nz = make_float4(0.f, 0.f, 0.f, 0.f);
        float4 cd = make_float4(0.f, 0.f, 0.f, 0.f);
        if ((unsigned)gy < (unsigned)IMH && (unsigned)gx < (unsigned)IMW) {
            const float* p = in + ((size_t)gy * IMW + gx) * CH;
            cd.x = p[0]; cd.y = p[1]; cd.z = p[2];      // col
            nz.x = p[3]; nz.y = p[4]; nz.z = p[5];      // nrm
            nz.w = p[9];                                 // z
            cd.w = p[10];                                // dz
        }
        s_nz[i] = nz;
        s_cd[i] = cd;
    }
    __syncthreads();

    // Pixel0 center; pixel1 is one smem row below (+SW).
    const int c0 = (threadIdx.y * PXY + RAD) * SW + (threadIdx.x + RAD);
    const float4* __restrict__ snz = s_nz + c0;
    const float4* __restrict__ scd = s_cd + c0;

    const float4 n0 = snz[0];
    const float  dz0 = scd[0].w;
    const float4 n1 = snz[SW];
    const float  dz1 = scd[SW].w;

    float ar0=0.f, ag0=0.f, ab0=0.f, aw0=0.f;
    float ar1=0.f, ag1=0.f, ab1=0.f, aw1=0.f;

    // dy spans pixel0's [-7,7] and pixel1's [-7,7] (shifted by +1):
    // one shared-memory load per (dy,dx) feeds both pixels.
    #pragma unroll
    for (int dy = -RAD; dy <= RAD + 1; ++dy) {
        #pragma unroll
        for (int dx = -RAD; dx <= RAD; ++dx) {
            const float4 nz = snz[dy*SW + dx];
            const float4 cd = scd[dy*SW + dx];

            if (dy <= RAD) {                       // compile-time predicate
                const int d0 = dy*dy + dx*dx;
                tap_(nz, cd, n0.x, n0.y, n0.z, n0.w, dz0,
                     (float)d0, sqrtf((float)d0), ar0, ag0, ab0, aw0);
            }
            if (dy >= -RAD + 1) {                  // compile-time predicate
                const int d1 = (dy-1)*(dy-1) + dx*dx;
                tap_(nz, cd, n1.x, n1.y, n1.z, n1.w, dz1,
                     (float)d1, sqrtf((float)d1), ar1, ag1, ab1, aw1);
            }
        }
    }

    const int gx = bx + threadIdx.x;
    const int gy0 = by + threadIdx.y * PXY;

    {
        const float inv = 1.0f / fmaxf(aw0, EPSF);
        float* o = out + ((size_t)gy0 * IMW + gx) * 3;
        o[0] = ar0 * inv; o[1] = ag0 * inv; o[2] = ab0 * inv;
    }
    {
        const float inv = 1.0f / fmaxf(aw1, EPSF);
        float* o = out + ((size_t)(gy0 + 1) * IMW + gx) * 3;
        o[0] = ar1 * inv; o[1] = ag1 * inv; o[2] = ab1 * inv;
    }
}

extern "C" void kernel_launch(void* const* d_in, const int* in_sizes, int n_in,
                              void* d_out, int out_size)
{
    const float* in = (const float*)d_in[0];
    float* out = (float*)d_out;
    dim3 block(TBX, TBY);
    dim3 grid(IMW / TBX, IMH / TILEY);   // 60 x 135, exact tiling
    BilateralDenoiser_44427141710593_kernel<<<grid, block>>>(in, out);
}